// round 3
// baseline (speedup 1.0000x reference)
#include <cuda_runtime.h>
#include <cstdint>

#define NODES 20000
#define BATCH 32
#define FEAT  64
#define EIG   16
#define NOUT  64

#define CHUNK1 512
#define NCHUNK 40        // ceil(NODES/CHUNK1)
#define TM1    64

#define TN3    128
#define NBLK3  157       // ceil(NODES/TN3)

typedef unsigned long long ull;

// Scratch (static device globals: allocation-free per harness rules)
__device__ float g_zpart[(size_t)NCHUNK * BATCH * FEAT * EIG]; // 5.24 MB
__device__ float g_z[BATCH * FEAT * EIG];                      // 128 KB
__device__ float g_w[BATCH * NOUT * EIG];                      // 128 KB

// ---- packed fp32x2 helpers (full-rate fp32 on sm_103a goes through FFMA2) ----
__device__ __forceinline__ ull pack2(float lo, float hi) {
    ull r; asm("mov.b64 %0, {%1, %2};" : "=l"(r) : "f"(lo), "f"(hi)); return r;
}
__device__ __forceinline__ float2 unpack2(ull v) {
    float2 r; asm("mov.b64 {%0, %1}, %2;" : "=f"(r.x), "=f"(r.y) : "l"(v)); return r;
}
__device__ __forceinline__ ull ffma2(ull a, ull b, ull c) {
    ull d; asm("fma.rn.f32x2 %0, %1, %2, %3;" : "=l"(d) : "l"(a), "l"(b), "l"(c)); return d;
}
__device__ __forceinline__ ull fmul2(ull a, ull b) {
    ull d; asm("mul.rn.f32x2 %0, %1, %2;" : "=l"(d) : "l"(a), "l"(b)); return d;
}
__device__ __forceinline__ ull fadd2(ull a, ull b) {
    ull d; asm("add.rn.f32x2 %0, %1, %2;" : "=l"(d) : "l"(a), "l"(b)); return d;
}

// ============================================================================
// Stage 1: z[b,i,f] = sum_m V[m,f] * x[b,m,i]
// Per-block: one batch, one 512-node chunk; partial z (64x16) -> g_zpart.
// Thread tile: 2 i-values x 4 f-values (4 FFMA2 accumulators).
// ============================================================================
__global__ __launch_bounds__(128)
void k1_project(const float* __restrict__ x, const float* __restrict__ V) {
    __shared__ __align__(16) float xs[TM1 * FEAT];  // 16 KB
    __shared__ __align__(16) float vs[TM1 * EIG];   //  4 KB
    const int b = blockIdx.y, c = blockIdx.x;
    const int m0 = c * CHUNK1;
    const int tid = threadIdx.x;
    const int i2 = tid & 31;   // i pair index: i = 2*i2, 2*i2+1
    const int fq = tid >> 5;   // f quad: f = 4*fq .. 4*fq+3
    ull a00 = 0ULL, a01 = 0ULL, a10 = 0ULL, a11 = 0ULL;
    const float* xb = x + (size_t)b * NODES * FEAT;

    for (int t = 0; t < CHUNK1; t += TM1) {
        const int mb = m0 + t;
        // cooperative load: x panel (64 nodes x 64 feat)
        #pragma unroll
        for (int r = 0; r < 8; r++) {
            int idx = r * 128 + tid;          // [0,1024) float4 slots
            int mm = idx >> 4, c4 = idx & 15;
            float4 v = make_float4(0.f, 0.f, 0.f, 0.f);
            if (mb + mm < NODES)
                v = *(const float4*)(xb + (size_t)(mb + mm) * FEAT + c4 * 4);
            *(float4*)(xs + mm * FEAT + c4 * 4) = v;
        }
        // cooperative load: V panel (64 nodes x 16 eig)
        #pragma unroll
        for (int r = 0; r < 2; r++) {
            int idx = r * 128 + tid;          // [0,256)
            int mm = idx >> 2, c4 = idx & 3;
            float4 v = make_float4(0.f, 0.f, 0.f, 0.f);
            if (mb + mm < NODES)
                v = *(const float4*)(V + (size_t)(mb + mm) * EIG + c4 * 4);
            *(float4*)(vs + mm * EIG + c4 * 4) = v;
        }
        __syncthreads();
        #pragma unroll
        for (int m = 0; m < TM1; m++) {
            float2 xv = *(const float2*)(xs + m * FEAT + i2 * 2);
            ulonglong2 vv = *(const ulonglong2*)(vs + m * EIG + fq * 4);
            ull xx0 = pack2(xv.x, xv.x);
            ull xx1 = pack2(xv.y, xv.y);
            a00 = ffma2(xx0, vv.x, a00);
            a01 = ffma2(xx0, vv.y, a01);
            a10 = ffma2(xx1, vv.x, a10);
            a11 = ffma2(xx1, vv.y, a11);
        }
        __syncthreads();
    }
    float* zp = g_zpart + ((size_t)c * BATCH + b) * (FEAT * EIG);
    float2 l0 = unpack2(a00), h0 = unpack2(a01);
    float2 l1 = unpack2(a10), h1 = unpack2(a11);
    *(float4*)(zp + (2 * i2)     * EIG + fq * 4) = make_float4(l0.x, l0.y, h0.x, h0.y);
    *(float4*)(zp + (2 * i2 + 1) * EIG + fq * 4) = make_float4(l1.x, l1.y, h1.x, h1.y);
}

// ============================================================================
// Stage 1b: reduce partial z over chunks (fixed order -> deterministic)
// ============================================================================
__global__ __launch_bounds__(256)
void k1_reduce() {
    const int q = blockIdx.x * 256 + threadIdx.x;   // over 8192 float4
    const float4* zp = (const float4*)g_zpart;
    float4 s = make_float4(0.f, 0.f, 0.f, 0.f);
    #pragma unroll
    for (int c = 0; c < NCHUNK; c++) {
        float4 v = zp[(size_t)c * (BATCH * FEAT * EIG / 4) + q];
        s.x += v.x; s.y += v.y; s.z += v.z; s.w += v.w;
    }
    ((float4*)g_z)[q] = s;
}

// ============================================================================
// Stage 2: w[b,j,e] = sum_{i,f} G[j,i,e,f] * z[b,i,f]
// Block = (batch-group of 8, j). z slab for 8 batches in smem (32 KB).
// Thread = (b_local, e); dot over i,f in packed pairs.
// ============================================================================
__global__ __launch_bounds__(128)
void k2_mix(const float* __restrict__ G) {
    __shared__ __align__(16) float zs[8 * FEAT * EIG];   // 32 KB
    const int bg = blockIdx.x;     // 0..3
    const int j  = blockIdx.y;     // 0..63
    const int tid = threadIdx.x;   // 128
    {
        const float4* src = (const float4*)(g_z + (size_t)bg * 8 * FEAT * EIG);
        float4* dst = (float4*)zs;
        #pragma unroll
        for (int r = 0; r < 16; r++) dst[r * 128 + tid] = src[r * 128 + tid];
    }
    __syncthreads();
    const int bl = tid >> 4;       // 0..7
    const int e  = tid & 15;
    const float* Gje  = G + (size_t)j * (FEAT * EIG * EIG) + e * EIG;
    const float* zrow = zs + bl * (FEAT * EIG);
    ull acc0 = 0ULL, acc1 = 0ULL, acc2 = 0ULL, acc3 = 0ULL;
    #pragma unroll 8
    for (int i = 0; i < FEAT; i++) {
        const ulonglong2* gp = (const ulonglong2*)(Gje + (size_t)i * (EIG * EIG));
        const ulonglong2* zq = (const ulonglong2*)(zrow + i * EIG);
        ulonglong2 g0 = gp[0], g1 = gp[1], g2 = gp[2], g3 = gp[3];
        ulonglong2 z0 = zq[0], z1 = zq[1], z2 = zq[2], z3 = zq[3];
        acc0 = ffma2(g0.x, z0.x, acc0);
        acc1 = ffma2(g0.y, z0.y, acc1);
        acc2 = ffma2(g1.x, z1.x, acc2);
        acc3 = ffma2(g1.y, z1.y, acc3);
        acc0 = ffma2(g2.x, z2.x, acc0);
        acc1 = ffma2(g2.y, z2.y, acc1);
        acc2 = ffma2(g3.x, z3.x, acc2);
        acc3 = ffma2(g3.y, z3.y, acc3);
    }
    ull s = fadd2(fadd2(acc0, acc1), fadd2(acc2, acc3));
    float2 f = unpack2(s);
    g_w[((size_t)bg * 8 + bl) * (NOUT * EIG) + j * EIG + e] = f.x + f.y;
}

// ============================================================================
// Stage 3: out[b,n,j] = sum_e V[n,e] * w[b,j,e]
// Block = (128-node chunk, batch). w[b] in smem -> registers (2 j per thread),
// V panel in smem. float2 coalesced stores.
// ============================================================================
__global__ __launch_bounds__(256)
void k3_expand(const float* __restrict__ V, float* __restrict__ out) {
    __shared__ __align__(16) float vs[TN3 * EIG];     // 8 KB
    __shared__ __align__(16) float ws[NOUT * EIG];    // 4 KB
    const int b  = blockIdx.y;
    const int n0 = blockIdx.x * TN3;
    const int tid = threadIdx.x;
    ((float4*)ws)[tid] = ((const float4*)(g_w + (size_t)b * NOUT * EIG))[tid];
    #pragma unroll
    for (int r = 0; r < 2; r++) {
        int idx = r * 256 + tid;            // [0,512) float4 slots
        int nn = idx >> 2, c4 = idx & 3;
        float4 v = make_float4(0.f, 0.f, 0.f, 0.f);
        if (n0 + nn < NODES)
            v = *(const float4*)(V + (size_t)(n0 + nn) * EIG + c4 * 4);
        *(float4*)(vs + nn * EIG + c4 * 4) = v;
    }
    __syncthreads();
    const int jp = tid & 31;     // j pair: j = 2*jp, 2*jp+1
    const int nb = tid >> 5;     // 0..7
    ull w0[8], w1[8];
    {
        const ulonglong2* p0 = (const ulonglong2*)(ws + (2 * jp) * EIG);
        ulonglong2 q0 = p0[0], q1 = p0[1], q2 = p0[2], q3 = p0[3];
        w0[0] = q0.x; w0[1] = q0.y; w0[2] = q1.x; w0[3] = q1.y;
        w0[4] = q2.x; w0[5] = q2.y; w0[6] = q3.x; w0[7] = q3.y;
        const ulonglong2* p1 = (const ulonglong2*)(ws + (2 * jp + 1) * EIG);
        ulonglong2 r0 = p1[0], r1 = p1[1], r2 = p1[2], r3 = p1[3];
        w1[0] = r0.x; w1[1] = r0.y; w1[2] = r1.x; w1[3] = r1.y;
        w1[4] = r2.x; w1[5] = r2.y; w1[6] = r3.x; w1[7] = r3.y;
    }
    float* ob = out + ((size_t)b * NODES + n0) * NOUT;
    #pragma unroll
    for (int p = 0; p < 16; p++) {
        const int nl = p * 8 + nb;
        const ulonglong2* vp = (const ulonglong2*)(vs + nl * EIG);
        ulonglong2 va = vp[0], vb = vp[1], vc = vp[2], vd = vp[3];
        ull a0 = fmul2(va.x, w0[0]);
        ull a1 = fmul2(va.y, w0[1]);
        a0 = ffma2(vb.x, w0[2], a0);
        a1 = ffma2(vb.y, w0[3], a1);
        a0 = ffma2(vc.x, w0[4], a0);
        a1 = ffma2(vc.y, w0[5], a1);
        a0 = ffma2(vd.x, w0[6], a0);
        a1 = ffma2(vd.y, w0[7], a1);
        float2 f0 = unpack2(fadd2(a0, a1));
        ull c0 = fmul2(va.x, w1[0]);
        ull c1 = fmul2(va.y, w1[1]);
        c0 = ffma2(vb.x, w1[2], c0);
        c1 = ffma2(vb.y, w1[3], c1);
        c0 = ffma2(vc.x, w1[4], c0);
        c1 = ffma2(vc.y, w1[5], c1);
        c0 = ffma2(vd.x, w1[6], c0);
        c1 = ffma2(vd.y, w1[7], c1);
        float2 f1 = unpack2(fadd2(c0, c1));
        if (n0 + nl < NODES)
            *(float2*)(ob + (size_t)nl * NOUT + 2 * jp) =
                make_float2(f0.x + f0.y, f1.x + f1.y);
    }
}

extern "C" void kernel_launch(void* const* d_in, const int* in_sizes, int n_in,
                              void* d_out, int out_size) {
    const float* x = (const float*)d_in[0];   // (32, 20000, 64) fp32
    const float* V = (const float*)d_in[1];   // (20000, 16)     fp32
    const float* G = (const float*)d_in[2];   // (64, 64, 16, 16) fp32
    float* out = (float*)d_out;               // (32, 20000, 64) fp32

    k1_project<<<dim3(NCHUNK, BATCH), 128>>>(x, V);
    k1_reduce<<<32, 256>>>();
    k2_mix<<<dim3(4, NOUT), 128>>>(G);
    k3_expand<<<dim3(NBLK3, BATCH), 256>>>(V, out);
}

// round 4
// speedup vs baseline: 1.1762x; 1.1762x over previous
#include <cuda_runtime.h>
#include <cstdint>

#define NODES 20000
#define BATCH 32
#define FEAT  64
#define EIG   16
#define NOUT  64

#define CHUNK1 500
#define NCHUNK 40        // 20000 = 40 * 500 exactly (no bounds checks in k1)

#define TN3    128
#define NBLK3  157       // ceil(NODES/TN3)

typedef unsigned long long ull;

// Scratch (static device globals: allocation-free per harness rules)
__device__ float g_zpart[(size_t)NCHUNK * BATCH * FEAT * EIG]; // 5.24 MB
__device__ float g_z[BATCH * FEAT * EIG];                      // 128 KB
__device__ float g_w[BATCH * NOUT * EIG];                      // 128 KB

// ---- packed fp32x2 helpers (full-rate fp32 on sm_103a goes through FFMA2) ----
__device__ __forceinline__ ull pack2(float lo, float hi) {
    ull r; asm("mov.b64 %0, {%1, %2};" : "=l"(r) : "f"(lo), "f"(hi)); return r;
}
__device__ __forceinline__ float2 unpack2(ull v) {
    float2 r; asm("mov.b64 {%0, %1}, %2;" : "=f"(r.x), "=f"(r.y) : "l"(v)); return r;
}
__device__ __forceinline__ ull ffma2(ull a, ull b, ull c) {
    ull d; asm("fma.rn.f32x2 %0, %1, %2, %3;" : "=l"(d) : "l"(a), "l"(b), "l"(c)); return d;
}
__device__ __forceinline__ ull fmul2(ull a, ull b) {
    ull d; asm("mul.rn.f32x2 %0, %1, %2;" : "=l"(d) : "l"(a), "l"(b)); return d;
}
__device__ __forceinline__ ull fadd2(ull a, ull b) {
    ull d; asm("add.rn.f32x2 %0, %1, %2;" : "=l"(d) : "l"(a), "l"(b)); return d;
}

// ============================================================================
// Stage 1: z[b,i,f] = sum_m V[m,f] * x[b,m,i]
// Block = (chunk c of 500 nodes, batch b), 256 threads = 8 warps.
// Warp w: stripe s = w>>1 handles m = s, s+4, ... ; lane covers i = (w&1)*32+lane.
// Thread owns ALL 16 f (8 FFMA2 accumulators); x read DIRECTLY from global
// (coalesced, read-once); V broadcast from smem (lane-invariant -> conflict-free).
// Epilogue: 4-stripe reduction via padded smem (aliases the V panel).
// ============================================================================
__global__ __launch_bounds__(256)
void k1_project(const float* __restrict__ x, const float* __restrict__ V) {
    __shared__ __align__(16) float sm[CHUNK1 * EIG];  // 32 KB; V panel, later red buf
    const int b = blockIdx.y, c = blockIdx.x;
    const int m0 = c * CHUNK1;
    const int tid = threadIdx.x;

    // cooperative load: V panel [500][16] (exact, no bounds: 20000 = 40*500)
    {
        const float4* src = (const float4*)(V + (size_t)m0 * EIG);
        float4* dst = (float4*)sm;
        #pragma unroll
        for (int r = 0; r < 8; r++) {
            int idx = r * 256 + tid;               // [0, 2000)
            if (idx < CHUNK1 * EIG / 4) dst[idx] = src[idx];
        }
    }
    __syncthreads();

    const int w = tid >> 5, lane = tid & 31;
    const int s = w >> 1;                 // stripe 0..3
    const int i = (w & 1) * 32 + lane;    // feature index 0..63
    const float* xb = x + ((size_t)b * NODES + m0) * FEAT + i;

    ull a0 = 0, a1 = 0, a2 = 0, a3 = 0, a4 = 0, a5 = 0, a6 = 0, a7 = 0;
    #pragma unroll 4
    for (int mi = s; mi < CHUNK1; mi += 4) {
        float xv = xb[(size_t)mi * FEAT];                       // coalesced LDG
        ull xx = pack2(xv, xv);
        const ulonglong2* vp = (const ulonglong2*)(sm + mi * EIG); // broadcast LDS
        ulonglong2 v0 = vp[0], v1 = vp[1], v2 = vp[2], v3 = vp[3];
        a0 = ffma2(xx, v0.x, a0);
        a1 = ffma2(xx, v0.y, a1);
        a2 = ffma2(xx, v1.x, a2);
        a3 = ffma2(xx, v1.y, a3);
        a4 = ffma2(xx, v2.x, a4);
        a5 = ffma2(xx, v2.y, a5);
        a6 = ffma2(xx, v3.x, a6);
        a7 = ffma2(xx, v3.y, a7);
    }
    __syncthreads();   // V panel no longer needed; reuse sm as padded red buffer

    // red[(s*64 + i)*20 + f], stride 20 floats (padding breaks bank alignment)
    {
        float* p = sm + (s * 64 + i) * 20;
        ulonglong2 t;
        t.x = a0; t.y = a1; *(ulonglong2*)(p + 0)  = t;
        t.x = a2; t.y = a3; *(ulonglong2*)(p + 4)  = t;
        t.x = a4; t.y = a5; *(ulonglong2*)(p + 8)  = t;
        t.x = a6; t.y = a7; *(ulonglong2*)(p + 12) = t;
    }
    __syncthreads();

    // reduce 4 stripes (fixed order -> deterministic), write partial z
    {
        const int ii = tid >> 2, fq = tid & 3;    // 64 i  x  4 f-quads
        float4 acc = make_float4(0.f, 0.f, 0.f, 0.f);
        #pragma unroll
        for (int ss = 0; ss < 4; ss++) {
            float4 v = *(const float4*)(sm + (ss * 64 + ii) * 20 + fq * 4);
            acc.x += v.x; acc.y += v.y; acc.z += v.z; acc.w += v.w;
        }
        *(float4*)(g_zpart + ((size_t)c * BATCH + b) * (FEAT * EIG)
                   + ii * EIG + fq * 4) = acc;
    }
}

// ============================================================================
// Stage 1b: reduce partial z over chunks (fixed order -> deterministic)
// ============================================================================
__global__ __launch_bounds__(256)
void k1_reduce() {
    const int q = blockIdx.x * 256 + threadIdx.x;   // over 8192 float4
    const float4* zp = (const float4*)g_zpart;
    float4 s = make_float4(0.f, 0.f, 0.f, 0.f);
    #pragma unroll
    for (int c = 0; c < NCHUNK; c++) {
        float4 v = zp[(size_t)c * (BATCH * FEAT * EIG / 4) + q];
        s.x += v.x; s.y += v.y; s.z += v.z; s.w += v.w;
    }
    ((float4*)g_z)[q] = s;
}

// ============================================================================
// Stage 2: w[b,j,e] = sum_{i,f} G[j,i,e,f] * z[b,i,f]
// ============================================================================
__global__ __launch_bounds__(128)
void k2_mix(const float* __restrict__ G) {
    __shared__ __align__(16) float zs[8 * FEAT * EIG];   // 32 KB
    const int bg = blockIdx.x;     // 0..3
    const int j  = blockIdx.y;     // 0..63
    const int tid = threadIdx.x;   // 128
    {
        const float4* src = (const float4*)(g_z + (size_t)bg * 8 * FEAT * EIG);
        float4* dst = (float4*)zs;
        #pragma unroll
        for (int r = 0; r < 16; r++) dst[r * 128 + tid] = src[r * 128 + tid];
    }
    __syncthreads();
    const int bl = tid >> 4;       // 0..7
    const int e  = tid & 15;
    const float* Gje  = G + (size_t)j * (FEAT * EIG * EIG) + e * EIG;
    const float* zrow = zs + bl * (FEAT * EIG);
    ull acc0 = 0ULL, acc1 = 0ULL, acc2 = 0ULL, acc3 = 0ULL;
    #pragma unroll 8
    for (int i = 0; i < FEAT; i++) {
        const ulonglong2* gp = (const ulonglong2*)(Gje + (size_t)i * (EIG * EIG));
        const ulonglong2* zq = (const ulonglong2*)(zrow + i * EIG);
        ulonglong2 g0 = gp[0], g1 = gp[1], g2 = gp[2], g3 = gp[3];
        ulonglong2 z0 = zq[0], z1 = zq[1], z2 = zq[2], z3 = zq[3];
        acc0 = ffma2(g0.x, z0.x, acc0);
        acc1 = ffma2(g0.y, z0.y, acc1);
        acc2 = ffma2(g1.x, z1.x, acc2);
        acc3 = ffma2(g1.y, z1.y, acc3);
        acc0 = ffma2(g2.x, z2.x, acc0);
        acc1 = ffma2(g2.y, z2.y, acc1);
        acc2 = ffma2(g3.x, z3.x, acc2);
        acc3 = ffma2(g3.y, z3.y, acc3);
    }
    ull s = fadd2(fadd2(acc0, acc1), fadd2(acc2, acc3));
    float2 f = unpack2(s);
    g_w[((size_t)bg * 8 + bl) * (NOUT * EIG) + j * EIG + e] = f.x + f.y;
}

// ============================================================================
// Stage 3: out[b,n,j] = sum_e V[n,e] * w[b,j,e]
// FIX vs R3: w staged TRANSPOSED + PADDED in smem (wsT[e][65]) so the
// per-thread w->register load is LDS.32 at 2-word lane stride (2-way max)
// instead of LDS.128 at 32-word stride (32-way bank conflict, the 82% L1).
// ============================================================================
__global__ __launch_bounds__(256)
void k3_expand(const float* __restrict__ V, float* __restrict__ out) {
    __shared__ __align__(16) float vs[TN3 * EIG];      // 8 KB
    __shared__ __align__(16) float wsT[EIG * 65];      // 4.2 KB, padded transpose
    const int b  = blockIdx.y;
    const int n0 = blockIdx.x * TN3;
    const int tid = threadIdx.x;

    // load w[b] transposed: wsT[e*65 + j] = w[b][j][e]
    {
        float4 fw = ((const float4*)(g_w + (size_t)b * NOUT * EIG))[tid];
        int j = tid >> 2, e0 = (tid & 3) * 4;
        wsT[(e0 + 0) * 65 + j] = fw.x;
        wsT[(e0 + 1) * 65 + j] = fw.y;
        wsT[(e0 + 2) * 65 + j] = fw.z;
        wsT[(e0 + 3) * 65 + j] = fw.w;
    }
    #pragma unroll
    for (int r = 0; r < 2; r++) {
        int idx = r * 256 + tid;            // [0,512) float4 slots
        int nn = idx >> 2, c4 = idx & 3;
        float4 v = make_float4(0.f, 0.f, 0.f, 0.f);
        if (n0 + nn < NODES)
            v = *(const float4*)(V + (size_t)(n0 + nn) * EIG + c4 * 4);
        *(float4*)(vs + nn * EIG + c4 * 4) = v;
    }
    __syncthreads();

    const int jp = tid & 31;     // j pair: j = 2*jp, 2*jp+1
    const int nb = tid >> 5;     // 0..7
    ull w0[8], w1[8];
    #pragma unroll
    for (int k = 0; k < 8; k++) {
        w0[k] = pack2(wsT[(2 * k) * 65 + 2 * jp],     wsT[(2 * k + 1) * 65 + 2 * jp]);
        w1[k] = pack2(wsT[(2 * k) * 65 + 2 * jp + 1], wsT[(2 * k + 1) * 65 + 2 * jp + 1]);
    }

    float* ob = out + ((size_t)b * NODES + n0) * NOUT;
    #pragma unroll
    for (int p = 0; p < 16; p++) {
        const int nl = p * 8 + nb;
        const ulonglong2* vp = (const ulonglong2*)(vs + nl * EIG);  // broadcast
        ulonglong2 va = vp[0], vb = vp[1], vc = vp[2], vd = vp[3];
        ull a0 = fmul2(va.x, w0[0]);
        ull a1 = fmul2(va.y, w0[1]);
        a0 = ffma2(vb.x, w0[2], a0);
        a1 = ffma2(vb.y, w0[3], a1);
        a0 = ffma2(vc.x, w0[4], a0);
        a1 = ffma2(vc.y, w0[5], a1);
        a0 = ffma2(vd.x, w0[6], a0);
        a1 = ffma2(vd.y, w0[7], a1);
        float2 f0 = unpack2(fadd2(a0, a1));
        ull c0 = fmul2(va.x, w1[0]);
        ull c1 = fmul2(va.y, w1[1]);
        c0 = ffma2(vb.x, w1[2], c0);
        c1 = ffma2(vb.y, w1[3], c1);
        c0 = ffma2(vc.x, w1[4], c0);
        c1 = ffma2(vc.y, w1[5], c1);
        c0 = ffma2(vd.x, w1[6], c0);
        c1 = ffma2(vd.y, w1[7], c1);
        float2 f1 = unpack2(fadd2(c0, c1));
        if (n0 + nl < NODES)
            *(float2*)(ob + (size_t)nl * NOUT + 2 * jp) =
                make_float2(f0.x + f0.y, f1.x + f1.y);
    }
}

extern "C" void kernel_launch(void* const* d_in, const int* in_sizes, int n_in,
                              void* d_out, int out_size) {
    const float* x = (const float*)d_in[0];   // (32, 20000, 64) fp32
    const float* V = (const float*)d_in[1];   // (20000, 16)     fp32
    const float* G = (const float*)d_in[2];   // (64, 64, 16, 16) fp32
    float* out = (float*)d_out;               // (32, 20000, 64) fp32

    k1_project<<<dim3(NCHUNK, BATCH), 256>>>(x, V);
    k1_reduce<<<32, 256>>>();
    k2_mix<<<dim3(4, NOUT), 128>>>(G);
    k3_expand<<<dim3(NBLK3, BATCH), 256>>>(V, out);
}